// round 3
// baseline (speedup 1.0000x reference)
#include <cuda_runtime.h>

// Problem shape (fixed by the dataset): B=4, S=4096, D=2048, W=4
#define BV 4
#define SV 4096
#define DV 2048
#define TOK 32   // tokens per score block

// Scratch (no allocations allowed) ------------------------------------------
__device__ int g_mask[BV * SV];
__device__ int g_src [BV * SV];

// Packed f32x2 helpers (FFMA2 — ptxas never emits these from C++) ------------
typedef unsigned long long u64;
static __device__ __forceinline__ u64 pk(float lo, float hi) {
    u64 r; asm("mov.b64 %0,{%1,%2};" : "=l"(r) : "f"(lo), "f"(hi)); return r;
}
static __device__ __forceinline__ void upk(u64 v, float& lo, float& hi) {
    asm("mov.b64 {%0,%1},%2;" : "=f"(lo), "=f"(hi) : "l"(v));
}
static __device__ __forceinline__ u64 f2fma(u64 a, u64 b, u64 c) {
    u64 d; asm("fma.rn.f32x2 %0,%1,%2,%3;" : "=l"(d) : "l"(a), "l"(b), "l"(c)); return d;
}
static __device__ __forceinline__ u64 f2mul(u64 a, u64 b) {
    u64 d; asm("mul.rn.f32x2 %0,%1,%2;" : "=l"(d) : "l"(a), "l"(b)); return d;
}

// K1: fused rmsnorm + causal dwconv(W=4) + silu + (p1-p0) dot -> sign/token.
// 512 threads, 4 channels/thread, 32 tokens/block. Rows processed in groups
// of 4 with a 4-row-deep prefetch (4 LDG.128 in flight per thread) and ONE
// __syncthreads per group (amortized rinv reduction, parity double-buffer).
__global__ void __launch_bounds__(512, 1) score_kernel(
    const float* __restrict__ x, const float* __restrict__ nw,
    const float* __restrict__ cw, const float* __restrict__ pw)
{
    const int b    = blockIdx.y;
    const int s0   = blockIdx.x * TOK;
    const int tid  = threadIdx.x;
    const int lane = tid & 31, wid = tid >> 5;   // wid 0..15
    const int c0   = tid * 4;

    __shared__ float wpart[2][4][16];   // sumsq warp partials (grp parity)
    __shared__ float spart[TOK][16];    // per-token score warp partials

    // Per-channel constants (packed pairs for 4 channels)
    u64 nv2[2], wv2[4][2];
    float gch[4];
#pragma unroll
    for (int j = 0; j < 2; j++) {
        int d = c0 + 2 * j;
        nv2[j] = pk(nw[d], nw[d + 1]);
#pragma unroll
        for (int wi = 0; wi < 4; wi++)
            wv2[wi][j] = pk(cw[d * 4 + wi], cw[(d + 1) * 4 + wi]);
    }
#pragma unroll
    for (int c = 0; c < 4; c++) gch[c] = pw[DV + c0 + c] - pw[c0 + c];

    u64 acc2[4][2];
#pragma unroll
    for (int s = 0; s < 4; s++) { acc2[s][0] = 0ull; acc2[s][1] = 0ull; }

    const float* xb = x + (size_t)b * SV * DV + c0;
    const float4 fz = make_float4(0.f, 0.f, 0.f, 0.f);

    // Prologue: prefetch group 0 (rows i=0..3, global r=s0-3+i)
    float4 pf[4];
#pragma unroll
    for (int k = 0; k < 4; k++) {
        int r = s0 - 3 + k;
        pf[k] = (r >= 0) ? *(const float4*)(xb + (size_t)r * DV) : fz;
    }

    // rows i = 0..34 (i=35 is padding); 9 groups of 4
#pragma unroll 1
    for (int grp = 0; grp < 9; grp++) {
        float4 cur[4];
#pragma unroll
        for (int k = 0; k < 4; k++) cur[k] = pf[k];

        // Prefetch next group (deep MLP: issued before any compute)
#pragma unroll
        for (int k = 0; k < 4; k++) {
            int i = grp * 4 + 4 + k;
            int r = s0 - 3 + i;
            pf[k] = (i < 35 && r >= 0) ? *(const float4*)(xb + (size_t)r * DV)
                                       : fz;
        }

        // Sum of squares for the 4 rows -> warp partials
        const int par = grp & 1;
#pragma unroll
        for (int k = 0; k < 4; k++) {
            float s = cur[k].x * cur[k].x + cur[k].y * cur[k].y
                    + cur[k].z * cur[k].z + cur[k].w * cur[k].w;
#pragma unroll
            for (int o = 16; o > 0; o >>= 1)
                s += __shfl_xor_sync(0xffffffffu, s, o);
            if (lane == 0) wpart[par][k][wid] = s;
        }
        __syncthreads();

        float rinv[4];
#pragma unroll
        for (int k = 0; k < 4; k++) {
            float tot = 0.f;
#pragma unroll
            for (int w = 0; w < 16; w++) tot += wpart[par][k][w];
            rinv[k] = rsqrtf(tot * (1.f / DV) + 1e-5f);
        }

        // Conv accumulate + token completion (ring slots compile-time in k)
#pragma unroll
        for (int k = 0; k < 4; k++) {
            const int i = grp * 4 + k;
            u64 x2[2] = { pk(cur[k].x, cur[k].y), pk(cur[k].z, cur[k].w) };
            const u64 ri2 = pk(rinv[k], rinv[k]);
            u64 h2[2];
#pragma unroll
            for (int j = 0; j < 2; j++)
                h2[j] = f2mul(f2mul(ri2, nv2[j]), x2[j]);

#pragma unroll
            for (int jj = 0; jj < 4; jj++) {
                const int slot = (k + 1 + jj) & 3;
#pragma unroll
                for (int j = 0; j < 2; j++)
                    acc2[slot][j] = f2fma(wv2[3 - jj][j], h2[j], acc2[slot][j]);
            }

            if (i >= 3 && i < 35) {
                const int slot = (k + 1) & 3;
                float p = 0.f;
#pragma unroll
                for (int j = 0; j < 2; j++) {
                    float v0, v1; upk(acc2[slot][j], v0, v1);
                    p += gch[2 * j]     * __fdividef(v0, 1.f + __expf(-v0));
                    p += gch[2 * j + 1] * __fdividef(v1, 1.f + __expf(-v1));
                }
#pragma unroll
                for (int o = 16; o > 0; o >>= 1)
                    p += __shfl_xor_sync(0xffffffffu, p, o);
                if (lane == 0) spart[i - 3][wid] = p;
            }
            {   // recycle slot for token i+1's window
                const int slot = (k + 1) & 3;
                acc2[slot][0] = 0ull; acc2[slot][1] = 0ull;
            }
        }
    }
    __syncthreads();
    if (tid < TOK) {
        float t = 0.f;
#pragma unroll
        for (int w = 0; w < 16; w++) t += spart[tid][w];
        g_mask[b * SV + s0 + tid] = (t > 0.f) ? 1 : 0;
    }
}

// K2: per-batch inclusive scan of masks -> inverse map src[b][c-1] = s -------
__global__ void __launch_bounds__(1024) scan_kernel() {
    const int b   = blockIdx.x;
    const int tid = threadIdx.x;
    for (int j = tid; j < SV; j += 1024) g_src[b * SV + j] = -1;
    __syncthreads();

    int base = tid * 4;
    int m[4], pre[4];
    int sum = 0;
#pragma unroll
    for (int k = 0; k < 4; k++) {
        m[k] = g_mask[b * SV + base + k];
        sum += m[k];
        pre[k] = sum;
    }
    int lane = tid & 31, wid = tid >> 5;
    int v = sum;
#pragma unroll
    for (int o = 1; o < 32; o <<= 1) {
        int t = __shfl_up_sync(0xffffffffu, v, o);
        if (lane >= o) v += t;
    }
    __shared__ int wsum[32];
    if (lane == 31) wsum[wid] = v;
    __syncthreads();
    if (wid == 0) {
        int t = wsum[lane];
#pragma unroll
        for (int o = 1; o < 32; o <<= 1) {
            int u = __shfl_up_sync(0xffffffffu, t, o);
            if (lane >= o) t += u;
        }
        wsum[lane] = t;
    }
    __syncthreads();
    int offset = (wid > 0 ? wsum[wid - 1] : 0) + (v - sum);
#pragma unroll
    for (int k = 0; k < 4; k++) {
        if (m[k]) g_src[b * SV + offset + pre[k] - 1] = base + k;
    }
}

// K3: row-wise gather of x (selected, packed) or zero-fill -------------------
__global__ void __launch_bounds__(256) scatter_kernel(
    const float* __restrict__ x, float* __restrict__ out)
{
    const int row = blockIdx.x;              // 0 .. B*S-1
    const int b   = row >> 12;               // S = 4096
    const int s   = g_src[row];
    float4* o = (float4*)(out + (size_t)row * DV) + threadIdx.x;
    if (s >= 0) {
        const float4* xr =
            (const float4*)(x + ((size_t)(b << 12) + s) * DV) + threadIdx.x;
        float4 v0 = __ldcs(xr);
        float4 v1 = __ldcs(xr + 256);
        __stcs(o, v0);
        __stcs(o + 256, v1);
    } else {
        float4 z = make_float4(0.f, 0.f, 0.f, 0.f);
        __stcs(o, z);
        __stcs(o + 256, z);
    }
}

extern "C" void kernel_launch(void* const* d_in, const int* in_sizes, int n_in,
                              void* d_out, int out_size) {
    const float* x  = (const float*)d_in[0];  // [B,S,D]
    const float* nw = (const float*)d_in[1];  // [D]
    const float* cw = (const float*)d_in[2];  // [D,4]
    const float* pw = (const float*)d_in[3];  // [2,D]
    float* out = (float*)d_out;               // [B,S,D]

    dim3 g1(SV / TOK, BV);
    score_kernel<<<g1, 512>>>(x, nw, cw, pw);
    scan_kernel<<<BV, 1024>>>();
    scatter_kernel<<<BV * SV, 256>>>(x, out);
}

// round 4
// speedup vs baseline: 1.4223x; 1.4223x over previous
#include <cuda_runtime.h>

// Problem shape (fixed by the dataset): B=4, S=4096, D=2048, W=4
#define BV 4
#define SV 4096
#define DV 2048
#define TOK 32   // tokens per score block

// Scratch (no allocations allowed) ------------------------------------------
__device__ int g_mask[BV * SV];
__device__ int g_src [BV * SV];

// Packed f32x2 helpers --------------------------------------------------------
typedef unsigned long long u64;
static __device__ __forceinline__ u64 pk(float lo, float hi) {
    u64 r; asm("mov.b64 %0,{%1,%2};" : "=l"(r) : "f"(lo), "f"(hi)); return r;
}
static __device__ __forceinline__ void upk(u64 v, float& lo, float& hi) {
    asm("mov.b64 {%0,%1},%2;" : "=f"(lo), "=f"(hi) : "l"(v));
}
static __device__ __forceinline__ u64 f2fma(u64 a, u64 b, u64 c) {
    u64 d; asm("fma.rn.f32x2 %0,%1,%2,%3;" : "=l"(d) : "l"(a), "l"(b), "l"(c)); return d;
}
static __device__ __forceinline__ u64 f2mul(u64 a, u64 b) {
    u64 d; asm("mul.rn.f32x2 %0,%1,%2;" : "=l"(d) : "l"(a), "l"(b)); return d;
}

// cp.async helpers ------------------------------------------------------------
static __device__ __forceinline__ void cpa16(unsigned dst, const void* src) {
    asm volatile("cp.async.ca.shared.global [%0], [%1], 16;"
                 :: "r"(dst), "l"(src));
}
static __device__ __forceinline__ void cpa_commit() {
    asm volatile("cp.async.commit_group;");
}
template <int N>
static __device__ __forceinline__ void cpa_wait() {
    asm volatile("cp.async.wait_group %0;" :: "n"(N));
}
static __device__ __forceinline__ void sts_zero16(unsigned dst) {
    asm volatile("st.shared.v4.b32 [%0],{%1,%1,%1,%1};" :: "r"(dst), "r"(0));
}

// K1: fused rmsnorm + causal dwconv(W=4) + silu + (p1-p0) dot -> sign/token.
// 256 threads, 8 ch/thread, TOK=32. x rows stream through a 5-slot SMEM ring
// via cp.async (4 rows in flight, no register payload). Each thread copies and
// consumes its own 32B. One parity-buffered block reduction per row for rinv.
__global__ void __launch_bounds__(256, 2) score_kernel(
    const float* __restrict__ x, const float* __restrict__ nw,
    const float* __restrict__ cw, const float* __restrict__ pw)
{
    const int b    = blockIdx.y;
    const int s0   = blockIdx.x * TOK;
    const int tid  = threadIdx.x;
    const int lane = tid & 31, wid = tid >> 5;
    const int c0   = tid * 8;

    __shared__ float4 ring[5][512];     // 5 slots x 8KB
    __shared__ float  wpart[2][8];      // rinv warp partials (row parity)
    __shared__ float  spart[TOK][8];    // per-token score warp partials

    unsigned ring_u32;
    {
        unsigned long long g;
        asm("cvta.to.shared.u64 %0, %1;" : "=l"(g) : "l"(ring));
        ring_u32 = (unsigned)g + (unsigned)(tid * 32);
    }

    // Constants: fold nw into conv taps -> wnv[tap][c] = cw[c][tap]*nw[c]
    u64 wnv2[4][4];
    float gch[8];
#pragma unroll
    for (int j = 0; j < 4; j++) {
        int d = c0 + 2 * j;
        float n0 = nw[d], n1 = nw[d + 1];
#pragma unroll
        for (int wi = 0; wi < 4; wi++)
            wnv2[wi][j] = pk(cw[d * 4 + wi] * n0, cw[(d + 1) * 4 + wi] * n1);
    }
#pragma unroll
    for (int c = 0; c < 8; c++) gch[c] = pw[DV + c0 + c] - pw[c0 + c];

    u64 acc2[4][4];
#pragma unroll
    for (int s = 0; s < 4; s++)
#pragma unroll
        for (int j = 0; j < 4; j++) acc2[s][j] = 0ull;

    const float* xb = x + (size_t)b * SV * DV + c0;

    // Producer: stage row i (global r = s0-3+i) into ring slot i%5.
    auto produce = [&](int i) {
        const int r = s0 - 3 + i;
        const unsigned dst = ring_u32 + (unsigned)((i % 5) * 8192);
        if (r >= 0) {
            const float* src = xb + (size_t)r * DV;
            cpa16(dst, src);
            cpa16(dst + 16, src + 4);
        } else {
            sts_zero16(dst);
            sts_zero16(dst + 16);
        }
        cpa_commit();
    };

#pragma unroll
    for (int i = 0; i < 4; i++) produce(i);

    // rows i = 0..34 (i=35 = flush padding)
#pragma unroll 1
    for (int base = 0; base < 36; base += 4) {
#pragma unroll
        for (int k = 0; k < 4; k++) {
            const int i = base + k;
            float4 a, q;
            if (i <= 34) {
                if (i <= 31)      cpa_wait<3>();
                else if (i == 32) cpa_wait<2>();
                else if (i == 33) cpa_wait<1>();
                else              cpa_wait<0>();
                const float4* slot = &ring[i % 5][tid * 2];
                a = slot[0]; q = slot[1];
                if (i + 4 <= 34) produce(i + 4);
            } else {
                a = make_float4(0.f, 0.f, 0.f, 0.f); q = a;
            }

            // Block-wide sum of squares -> rinv (parity double-buffered)
            float ssq = a.x * a.x + a.y * a.y + a.z * a.z + a.w * a.w
                      + q.x * q.x + q.y * q.y + q.z * q.z + q.w * q.w;
#pragma unroll
            for (int o = 16; o > 0; o >>= 1)
                ssq += __shfl_xor_sync(0xffffffffu, ssq, o);
            const int par = i & 1;
            if (lane == 0) wpart[par][wid] = ssq;
            __syncthreads();
            float tot = 0.f;
#pragma unroll
            for (int w = 0; w < 8; w++) tot += wpart[par][w];
            const float ri = rsqrtf(tot * (1.f / DV) + 1e-5f);

            // xr = x * rinv (nw folded into taps)
            const u64 ri2 = pk(ri, ri);
            u64 xr2[4] = { f2mul(ri2, pk(a.x, a.y)), f2mul(ri2, pk(a.z, a.w)),
                           f2mul(ri2, pk(q.x, q.y)), f2mul(ri2, pk(q.z, q.w)) };

            // row contributes tap (3-jj) to token (row+jj)
#pragma unroll
            for (int jj = 0; jj < 4; jj++) {
                const int slot = (k + 1 + jj) & 3;
#pragma unroll
                for (int j = 0; j < 4; j++)
                    acc2[slot][j] = f2fma(wnv2[3 - jj][j], xr2[j], acc2[slot][j]);
            }

            // Token complete after its own row: silu + gate-dot + reduce
            if (i >= 3 && i < 35) {
                const int slot = (k + 1) & 3;
                float p = 0.f;
#pragma unroll
                for (int j = 0; j < 4; j++) {
                    float v0, v1; upk(acc2[slot][j], v0, v1);
                    p += gch[2 * j]     * __fdividef(v0, 1.f + __expf(-v0));
                    p += gch[2 * j + 1] * __fdividef(v1, 1.f + __expf(-v1));
                }
#pragma unroll
                for (int o = 16; o > 0; o >>= 1)
                    p += __shfl_xor_sync(0xffffffffu, p, o);
                if (lane == 0) spart[i - 3][wid] = p;
            }
            {   // recycle slot
                const int slot = (k + 1) & 3;
#pragma unroll
                for (int j = 0; j < 4; j++) acc2[slot][j] = 0ull;
            }
        }
    }
    __syncthreads();
    if (tid < TOK) {
        float t = 0.f;
#pragma unroll
        for (int w = 0; w < 8; w++) t += spart[tid][w];
        g_mask[b * SV + s0 + tid] = (t > 0.f) ? 1 : 0;
    }
}

// K2: per-batch inclusive scan of masks -> inverse map src[b][c-1] = s -------
__global__ void __launch_bounds__(1024) scan_kernel() {
    const int b   = blockIdx.x;
    const int tid = threadIdx.x;
    for (int j = tid; j < SV; j += 1024) g_src[b * SV + j] = -1;
    __syncthreads();

    int base = tid * 4;
    int m[4], pre[4];
    int sum = 0;
#pragma unroll
    for (int k = 0; k < 4; k++) {
        m[k] = g_mask[b * SV + base + k];
        sum += m[k];
        pre[k] = sum;
    }
    int lane = tid & 31, wid = tid >> 5;
    int v = sum;
#pragma unroll
    for (int o = 1; o < 32; o <<= 1) {
        int t = __shfl_up_sync(0xffffffffu, v, o);
        if (lane >= o) v += t;
    }
    __shared__ int wsum[32];
    if (lane == 31) wsum[wid] = v;
    __syncthreads();
    if (wid == 0) {
        int t = wsum[lane];
#pragma unroll
        for (int o = 1; o < 32; o <<= 1) {
            int u = __shfl_up_sync(0xffffffffu, t, o);
            if (lane >= o) t += u;
        }
        wsum[lane] = t;
    }
    __syncthreads();
    int offset = (wid > 0 ? wsum[wid - 1] : 0) + (v - sum);
#pragma unroll
    for (int k = 0; k < 4; k++) {
        if (m[k]) g_src[b * SV + offset + pre[k] - 1] = base + k;
    }
}

// K3: row-wise gather of x (selected, packed) or zero-fill -------------------
__global__ void __launch_bounds__(256) scatter_kernel(
    const float* __restrict__ x, float* __restrict__ out)
{
    const int row = blockIdx.x;              // 0 .. B*S-1
    const int b   = row >> 12;               // S = 4096
    const int s   = g_src[row];
    float4* o = (float4*)(out + (size_t)row * DV) + threadIdx.x;
    if (s >= 0) {
        const float4* xr =
            (const float4*)(x + ((size_t)(b << 12) + s) * DV) + threadIdx.x;
        float4 v0 = __ldcs(xr);
        float4 v1 = __ldcs(xr + 256);
        __stcs(o, v0);
        __stcs(o + 256, v1);
    } else {
        float4 z = make_float4(0.f, 0.f, 0.f, 0.f);
        __stcs(o, z);
        __stcs(o + 256, z);
    }
}

extern "C" void kernel_launch(void* const* d_in, const int* in_sizes, int n_in,
                              void* d_out, int out_size) {
    const float* x  = (const float*)d_in[0];  // [B,S,D]
    const float* nw = (const float*)d_in[1];  // [D]
    const float* cw = (const float*)d_in[2];  // [D,4]
    const float* pw = (const float*)d_in[3];  // [2,D]
    float* out = (float*)d_out;               // [B,S,D]

    dim3 g1(SV / TOK, BV);
    score_kernel<<<g1, 256>>>(x, nw, cw, pw);
    scan_kernel<<<BV, 1024>>>();
    scatter_kernel<<<BV * SV, 256>>>(x, out);
}

// round 5
// speedup vs baseline: 1.4828x; 1.0425x over previous
#include <cuda_runtime.h>

// Problem shape (fixed by the dataset): B=4, S=4096, D=2048, W=4
#define BV 4
#define SV 4096
#define DV 2048
#define TOK 64            // tokens per score block
#define NROWS (TOK + 3)   // 67 real rows (3-row causal halo)
#define NGRP 17           // 68 rows incl. 1 pad row, 4 rows/group
#define RSLOT 12          // ring slots (12 x 8KB = 96KB dynamic smem)

// Scratch (no allocations allowed) ------------------------------------------
__device__ int g_mask[BV * SV];
__device__ int g_src [BV * SV];

// Packed f32x2 helpers --------------------------------------------------------
typedef unsigned long long u64;
static __device__ __forceinline__ u64 pk(float lo, float hi) {
    u64 r; asm("mov.b64 %0,{%1,%2};" : "=l"(r) : "f"(lo), "f"(hi)); return r;
}
static __device__ __forceinline__ void upk(u64 v, float& lo, float& hi) {
    asm("mov.b64 {%0,%1},%2;" : "=f"(lo), "=f"(hi) : "l"(v));
}
static __device__ __forceinline__ u64 f2fma(u64 a, u64 b, u64 c) {
    u64 d; asm("fma.rn.f32x2 %0,%1,%2,%3;" : "=l"(d) : "l"(a), "l"(b), "l"(c)); return d;
}
static __device__ __forceinline__ u64 f2mul(u64 a, u64 b) {
    u64 d; asm("mul.rn.f32x2 %0,%1,%2;" : "=l"(d) : "l"(a), "l"(b)); return d;
}

// cp.async helpers ------------------------------------------------------------
static __device__ __forceinline__ void cpa16(unsigned dst, const void* src) {
    asm volatile("cp.async.ca.shared.global [%0], [%1], 16;"
                 :: "r"(dst), "l"(src));
}
static __device__ __forceinline__ void cpa_commit() {
    asm volatile("cp.async.commit_group;");
}
template <int N>
static __device__ __forceinline__ void cpa_wait() {
    asm volatile("cp.async.wait_group %0;" :: "n"(N));
}
static __device__ __forceinline__ void sts_zero16(unsigned dst) {
    asm volatile("st.shared.v4.b32 [%0],{%1,%1,%1,%1};" :: "r"(dst), "r"(0));
}

// K1: fused rmsnorm + causal dwconv(W=4) + silu + (p1-p0) dot -> sign/token.
// 256 threads, 8 ch/thread, 64 tokens/block. Rows stream through a 12-slot
// cp.async ring, processed in groups of 4 with ONE barrier per group
// (parity-buffered rinv partials). Each thread copies/consumes its own 32B,
// so the ring needs no barriers at all.
__global__ void __launch_bounds__(256, 2) score_kernel(
    const float* __restrict__ x, const float* __restrict__ nw,
    const float* __restrict__ cw, const float* __restrict__ pw)
{
    extern __shared__ float4 ring[];    // [RSLOT][512] : 12 x 8KB
    __shared__ float wpart[2][4][8];    // rinv warp partials (group parity)
    __shared__ float spart[TOK][8];     // per-token score warp partials

    const int b    = blockIdx.y;
    const int s0   = blockIdx.x * TOK;
    const int tid  = threadIdx.x;
    const int lane = tid & 31, wid = tid >> 5;
    const int c0   = tid * 8;

    unsigned ring_u32;
    {
        unsigned long long g;
        asm("cvta.to.shared.u64 %0, %1;" : "=l"(g) : "l"(ring));
        ring_u32 = (unsigned)g + (unsigned)(tid * 32);
    }

    // Constants: fold nw into conv taps -> wnv[tap][c] = cw[c][tap]*nw[c]
    u64 wnv2[4][4];
    float gch[8];
#pragma unroll
    for (int j = 0; j < 4; j++) {
        int d = c0 + 2 * j;
        float n0 = nw[d], n1 = nw[d + 1];
#pragma unroll
        for (int wi = 0; wi < 4; wi++)
            wnv2[wi][j] = pk(cw[d * 4 + wi] * n0, cw[(d + 1) * 4 + wi] * n1);
    }
#pragma unroll
    for (int c = 0; c < 8; c++) gch[c] = pw[DV + c0 + c] - pw[c0 + c];

    u64 acc2[4][4];
#pragma unroll
    for (int s = 0; s < 4; s++)
#pragma unroll
        for (int j = 0; j < 4; j++) acc2[s][j] = 0ull;

    const float* xb = x + (size_t)b * SV * DV + c0;

    // Stage rows 4g..4g+3 into the ring; one commit group per row-group.
    auto produce_group = [&](int g) {
        if (g < NGRP) {
#pragma unroll
            for (int k = 0; k < 4; k++) {
                const int i = 4 * g + k;
                const int r = s0 - 3 + i;
                const unsigned dst = ring_u32 + (unsigned)((i % RSLOT) * 8192);
                if (i < NROWS && r >= 0) {
                    const float* src = xb + (size_t)r * DV;
                    cpa16(dst, src);
                    cpa16(dst + 16, src + 4);
                } else {
                    sts_zero16(dst);
                    sts_zero16(dst + 16);
                }
            }
        }
        cpa_commit();   // empty commit keeps wait_group accounting uniform
    };

    produce_group(0);
    produce_group(1);

#pragma unroll 1
    for (int g = 0; g < NGRP; g++) {
        cpa_wait<1>();   // groups 0..g landed (g+1 may be in flight)

        // Pull the 4 rows into registers (own 32B -> no barrier needed)
        float4 a[4], q[4];
#pragma unroll
        for (int k = 0; k < 4; k++) {
            const int i = 4 * g + k;
            const float4* slot = &ring[(i % RSLOT) * 512 + tid * 2];
            a[k] = slot[0]; q[k] = slot[1];
        }
        produce_group(g + 2);

        // 4 parallel block reductions for rinv (one barrier per group)
        const int par = g & 1;
#pragma unroll
        for (int k = 0; k < 4; k++) {
            float s = a[k].x * a[k].x + a[k].y * a[k].y
                    + a[k].z * a[k].z + a[k].w * a[k].w
                    + q[k].x * q[k].x + q[k].y * q[k].y
                    + q[k].z * q[k].z + q[k].w * q[k].w;
#pragma unroll
            for (int o = 16; o > 0; o >>= 1)
                s += __shfl_xor_sync(0xffffffffu, s, o);
            if (lane == 0) wpart[par][k][wid] = s;
        }
        __syncthreads();

        float rinv[4];
#pragma unroll
        for (int k = 0; k < 4; k++) {
            float tot = 0.f;
#pragma unroll
            for (int w = 0; w < 8; w++) tot += wpart[par][k][w];
            rinv[k] = rsqrtf(tot * (1.f / DV) + 1e-5f);
        }

        // Conv accumulate + token completion (ring slots compile-time in k)
#pragma unroll
        for (int k = 0; k < 4; k++) {
            const int i = 4 * g + k;
            const u64 ri2 = pk(rinv[k], rinv[k]);
            u64 xr2[4] = { f2mul(ri2, pk(a[k].x, a[k].y)),
                           f2mul(ri2, pk(a[k].z, a[k].w)),
                           f2mul(ri2, pk(q[k].x, q[k].y)),
                           f2mul(ri2, pk(q[k].z, q[k].w)) };

#pragma unroll
            for (int jj = 0; jj < 4; jj++) {
                const int slot = (k + 1 + jj) & 3;
#pragma unroll
                for (int j = 0; j < 4; j++)
                    acc2[slot][j] = f2fma(wnv2[3 - jj][j], xr2[j], acc2[slot][j]);
            }

            if (i >= 3 && i < NROWS) {
                const int slot = (k + 1) & 3;
                float p = 0.f;
#pragma unroll
                for (int j = 0; j < 4; j++) {
                    float v0, v1; upk(acc2[slot][j], v0, v1);
                    p += gch[2 * j]     * __fdividef(v0, 1.f + __expf(-v0));
                    p += gch[2 * j + 1] * __fdividef(v1, 1.f + __expf(-v1));
                }
#pragma unroll
                for (int o = 16; o > 0; o >>= 1)
                    p += __shfl_xor_sync(0xffffffffu, p, o);
                if (lane == 0) spart[i - 3][wid] = p;
            }
            {   // recycle slot
                const int slot = (k + 1) & 3;
#pragma unroll
                for (int j = 0; j < 4; j++) acc2[slot][j] = 0ull;
            }
        }
    }
    __syncthreads();
    if (tid < TOK) {
        float t = 0.f;
#pragma unroll
        for (int w = 0; w < 8; w++) t += spart[tid][w];
        g_mask[b * SV + s0 + tid] = (t > 0.f) ? 1 : 0;
    }
}

// K2: per-batch inclusive scan of masks -> inverse map src[b][c-1] = s -------
__global__ void __launch_bounds__(1024) scan_kernel() {
    const int b   = blockIdx.x;
    const int tid = threadIdx.x;
    for (int j = tid; j < SV; j += 1024) g_src[b * SV + j] = -1;
    __syncthreads();

    int base = tid * 4;
    int m[4], pre[4];
    int sum = 0;
#pragma unroll
    for (int k = 0; k < 4; k++) {
        m[k] = g_mask[b * SV + base + k];
        sum += m[k];
        pre[k] = sum;
    }
    int lane = tid & 31, wid = tid >> 5;
    int v = sum;
#pragma unroll
    for (int o = 1; o < 32; o <<= 1) {
        int t = __shfl_up_sync(0xffffffffu, v, o);
        if (lane >= o) v += t;
    }
    __shared__ int wsum[32];
    if (lane == 31) wsum[wid] = v;
    __syncthreads();
    if (wid == 0) {
        int t = wsum[lane];
#pragma unroll
        for (int o = 1; o < 32; o <<= 1) {
            int u = __shfl_up_sync(0xffffffffu, t, o);
            if (lane >= o) t += u;
        }
        wsum[lane] = t;
    }
    __syncthreads();
    int offset = (wid > 0 ? wsum[wid - 1] : 0) + (v - sum);
#pragma unroll
    for (int k = 0; k < 4; k++) {
        if (m[k]) g_src[b * SV + offset + pre[k] - 1] = base + k;
    }
}

// K3: row-wise gather of x (selected, packed) or zero-fill -------------------
__global__ void __launch_bounds__(256) scatter_kernel(
    const float* __restrict__ x, float* __restrict__ out)
{
    const int row = blockIdx.x;              // 0 .. B*S-1
    const int b   = row >> 12;               // S = 4096
    const int s   = g_src[row];
    float4* o = (float4*)(out + (size_t)row * DV) + threadIdx.x;
    if (s >= 0) {
        const float4* xr =
            (const float4*)(x + ((size_t)(b << 12) + s) * DV) + threadIdx.x;
        float4 v0 = __ldcs(xr);
        float4 v1 = __ldcs(xr + 256);
        __stcs(o, v0);
        __stcs(o + 256, v1);
    } else {
        float4 z = make_float4(0.f, 0.f, 0.f, 0.f);
        __stcs(o, z);
        __stcs(o + 256, z);
    }
}

extern "C" void kernel_launch(void* const* d_in, const int* in_sizes, int n_in,
                              void* d_out, int out_size) {
    const float* x  = (const float*)d_in[0];  // [B,S,D]
    const float* nw = (const float*)d_in[1];  // [D]
    const float* cw = (const float*)d_in[2];  // [D,4]
    const float* pw = (const float*)d_in[3];  // [2,D]
    float* out = (float*)d_out;               // [B,S,D]

    const int ring_bytes = RSLOT * 8192;      // 96KB dynamic smem
    cudaFuncSetAttribute(score_kernel,
                         cudaFuncAttributeMaxDynamicSharedMemorySize,
                         ring_bytes);

    dim3 g1(SV / TOK, BV);
    score_kernel<<<g1, 256, ring_bytes>>>(x, nw, cw, pw);
    scan_kernel<<<BV, 1024>>>();
    scatter_kernel<<<BV * SV, 256>>>(x, out);
}